// round 6
// baseline (speedup 1.0000x reference)
#include <cuda_runtime.h>
#include <cuda_fp16.h>

// Problem constants (fixed shapes):
//   x:      (16, 256, 64, 64)  fp32
//   weight: (8, 256)           fp32
//   bias:   (8,)               fp32
//   out:    (16, 256, 128, 128) fp32
#define Bn  16
#define Cn  256
#define Hn  64
#define Wn  64
#define OYn 128
#define OXn 128
#define PLANE (Hn * Wn)        // 4096
#define PADW 65                // padded row stride (uint2 cells)
#define NPX  (OYn * OXn)       // 16384

// fp16-packed input, 4 channels per uint2 cell: [b][cg][h*64+w]. 32 MB.
__device__ uint2 g_xh[Bn * 64 * PLANE];
// Per-pixel sample descriptor (8 B): {half2(wx,wy),
//   base(14b) | dx<<14 | dy<<15 | zx0<<16 | zx1<<17 | zy0<<18 | zy1<<19}
__device__ uint2 g_samp[Bn * NPX];

__device__ __forceinline__ uint2 packh4(float a, float b, float c, float d)
{
    __half2 lo = __floats2half2_rn(a, b);
    __half2 hi = __floats2half2_rn(c, d);
    uint2 r;
    r.x = *reinterpret_cast<unsigned int*>(&lo);
    r.y = *reinterpret_cast<unsigned int*>(&hi);
    return r;
}

// ---------------------------------------------------------------------------
// Stage 1: 1x1 conv + pixel shuffle + FULL sample-descriptor precompute +
// fp16 repack of x. Block = one (b, h) row, threads = (w, cpart).
// ---------------------------------------------------------------------------
__global__ __launch_bounds__(256) void dysample_stage1(
    const float* __restrict__ x,
    const float* __restrict__ weight,
    const float* __restrict__ bias)
{
    __shared__ float wt[Cn * 8];          // transposed: wt[c*8+o]
    __shared__ float part[3][64][9];

    for (int i = threadIdx.x; i < Cn * 8; i += 256)
        wt[(i & 255) * 8 + (i >> 8)] = weight[i];
    __syncthreads();

    int w     = threadIdx.x & 63;
    int cpart = threadIdx.x >> 6;         // 0..3
    int b     = blockIdx.x >> 6;
    int h     = blockIdx.x & 63;

    const float* xb  = x + ((size_t)b * Cn + cpart * 64) * PLANE + h * Wn + w;
    const float* wr0 = &wt[(cpart * 64) * 8];
    uint2* xhb = g_xh + ((size_t)(b * 64 + cpart * 16)) * PLANE + h * Wn + w;

    float acc[8];
#pragma unroll
    for (int s = 0; s < 8; s++) acc[s] = 0.0f;

#pragma unroll 4
    for (int c4 = 0; c4 < 16; ++c4) {
        float v0 = __ldg(xb + (size_t)(c4 * 4 + 0) * PLANE);
        float v1 = __ldg(xb + (size_t)(c4 * 4 + 1) * PLANE);
        float v2 = __ldg(xb + (size_t)(c4 * 4 + 2) * PLANE);
        float v3 = __ldg(xb + (size_t)(c4 * 4 + 3) * PLANE);
#pragma unroll
        for (int j = 0; j < 4; ++j) {
            float xv = (j == 0) ? v0 : (j == 1) ? v1 : (j == 2) ? v2 : v3;
            const float* wr = wr0 + (c4 * 4 + j) * 8;
            float4 wa = *reinterpret_cast<const float4*>(wr);
            float4 wb = *reinterpret_cast<const float4*>(wr + 4);
            acc[0] = fmaf(xv, wa.x, acc[0]);
            acc[1] = fmaf(xv, wa.y, acc[1]);
            acc[2] = fmaf(xv, wa.z, acc[2]);
            acc[3] = fmaf(xv, wa.w, acc[3]);
            acc[4] = fmaf(xv, wb.x, acc[4]);
            acc[5] = fmaf(xv, wb.y, acc[5]);
            acc[6] = fmaf(xv, wb.z, acc[6]);
            acc[7] = fmaf(xv, wb.w, acc[7]);
        }
        // fp16 repack (coalesced STG.64 along w)
        xhb[(size_t)c4 * PLANE] = packh4(v0, v1, v2, v3);
    }

    if (cpart != 0) {
#pragma unroll
        for (int s = 0; s < 8; s++) part[cpart - 1][w][s] = acc[s];
    }
    __syncthreads();

    if (cpart == 0) {
#pragma unroll
        for (int s = 0; s < 8; s++)
            acc[s] += part[0][w][s] + part[1][w][s] + part[2][w][s]
                    + __ldg(&bias[s]);

        // pixel shuffle: out (oy=2h+r1, ox=2w+r2) uses channels s=r1*2+r2
        // (x-coord) and 4+s (y-coord). Reference quirk: x-coord uses the
        // h-linspace at oy; y-coord uses w-linspace at ox.
#pragma unroll
        for (int s = 0; s < 4; s++) {
            int oy = 2 * h + (s >> 1);
            int ox = 2 * w + (s & 1);
            float gx = fmaf((float)oy, 2.0f / 127.0f, -1.0f) + acc[s];
            float gy = fmaf((float)ox, 2.0f / 127.0f, -1.0f) + acc[4 + s];
            float ix = fmaf(gx, 32.0f, 31.5f);   // ((g+1)*64 - 1)/2
            float iy = fmaf(gy, 32.0f, 31.5f);

            float fx = floorf(ix), fy = floorf(iy);
            int x0 = (int)fx, y0 = (int)fy;
            float wx = ix - fx, wy = iy - fy;

            int xc0 = min(max(x0, 0), Wn - 1);
            int xc1 = min(max(x0 + 1, 0), Wn - 1);
            int yc0 = min(max(y0, 0), Hn - 1);
            int yc1 = min(max(y0 + 1, 0), Hn - 1);
            unsigned dx = (unsigned)(xc1 - xc0);          // 0 or 1
            unsigned dy = (unsigned)(yc1 - yc0);
            unsigned zx0 = ((unsigned)x0       > 63u) ? 1u : 0u;
            unsigned zx1 = ((unsigned)(x0 + 1) > 63u) ? 1u : 0u;
            unsigned zy0 = ((unsigned)y0       > 63u) ? 1u : 0u;
            unsigned zy1 = ((unsigned)(y0 + 1) > 63u) ? 1u : 0u;

            unsigned idx = (unsigned)(yc0 * PADW + xc0)
                         | (dx << 14) | (dy << 15)
                         | (zx0 << 16) | (zx1 << 17)
                         | (zy0 << 18) | (zy1 << 19);
            __half2 wxy = __floats2half2_rn(wx, wy);
            uint2 rec;
            rec.x = *reinterpret_cast<unsigned int*>(&wxy);
            rec.y = idx;
            g_samp[(size_t)b * NPX + oy * OXn + ox] = rec;
        }
    }
}

// ---------------------------------------------------------------------------
// Stage 2: bilinear blend only. Block = (b, cg quad, pixel-quarter).
// Staging is a straight uint4 copy from pre-packed g_xh; per-pixel weights
// reconstructed from the 8 B descriptor (no floor/clamp per quad).
// ---------------------------------------------------------------------------
__device__ __forceinline__ void unpack4(uint2 v, float2& p01, float2& p23)
{
    p01 = __half22float2(*reinterpret_cast<const __half2*>(&v.x));
    p23 = __half22float2(*reinterpret_cast<const __half2*>(&v.y));
}

__device__ __forceinline__ float4 sample_one(const uint2* __restrict__ plane,
                                             unsigned wbits, unsigned idx)
{
    float2 wxy = __half22float2(*reinterpret_cast<const __half2*>(&wbits));
    float wx = wxy.x, wy = wxy.y;

    int base = idx & 0x3FFF;
    int dx   = (idx >> 14) & 1;
    int dy   = (idx >> 15) & 1;
    float ax0 = (idx & (1u << 16)) ? 0.0f : (1.0f - wx);
    float ax1 = (idx & (1u << 17)) ? 0.0f : wx;
    float ay0 = (idx & (1u << 18)) ? 0.0f : (1.0f - wy);
    float ay1 = (idx & (1u << 19)) ? 0.0f : wy;

    float w00 = ay0 * ax0, w01 = ay0 * ax1;
    float w10 = ay1 * ax0, w11 = ay1 * ax1;

    const uint2* r0p = plane + base;
    const uint2* r1p = r0p + (dy ? PADW : 0);
    uint2 v00 = r0p[0], v01 = r0p[dx];
    uint2 v10 = r1p[0], v11 = r1p[dx];

    float2 a01, a23, b01, b23;
    unpack4(v00, a01, a23);
    unpack4(v01, b01, b23);
    float rx = a01.x * w00 + b01.x * w01;
    float ry = a01.y * w00 + b01.y * w01;
    float rz = a23.x * w00 + b23.x * w01;
    float rw = a23.y * w00 + b23.y * w01;
    unpack4(v10, a01, a23);
    unpack4(v11, b01, b23);
    rx = fmaf(a01.x, w10, fmaf(b01.x, w11, rx));
    ry = fmaf(a01.y, w10, fmaf(b01.y, w11, ry));
    rz = fmaf(a23.x, w10, fmaf(b23.x, w11, rz));
    rw = fmaf(a23.y, w10, fmaf(b23.y, w11, rw));
    return make_float4(rx, ry, rz, rw);
}

__global__ __launch_bounds__(256, 6) void dysample_stage2(
    float* __restrict__ out)
{
    __shared__ uint2 plane[Hn * PADW];    // 33,280 B -> 6 blocks/SM

    int bid = blockIdx.x;                 // 0..4095
    int q   = bid & 3;                    // pixel quarter
    int cg  = (bid >> 2) & 63;            // channel quad
    int b   = bid >> 8;                   // batch

    // Stage the pre-packed plane: 4096 cells, 2 per thread per iter.
    const uint2* src = g_xh + ((size_t)(b * 64 + cg)) * PLANE;
#pragma unroll
    for (int k = 0; k < 8; ++k) {
        int i = k * 512 + threadIdx.x * 2;
        uint4 v = *reinterpret_cast<const uint4*>(src + i);
        int row = i >> 6, col = i & 63;
        plane[row * PADW + col]     = make_uint2(v.x, v.y);
        plane[row * PADW + col + 1] = make_uint2(v.z, v.w);
    }
    __syncthreads();

    const uint2* samp = g_samp + (size_t)b * NPX;
    float* o0 = out + ((size_t)(b * Cn + cg * 4)) * NPX;
    float* o1 = o0 + NPX;
    float* o2 = o1 + NPX;
    float* o3 = o2 + NPX;

    // This block's quarter: 4096 pixels, 2 per thread -> 8 iterations.
#pragma unroll 2
    for (int it = 0; it < 8; ++it) {
        int p = q * 4096 + it * 512 + threadIdx.x * 2;
        uint4 sv = *reinterpret_cast<const uint4*>(samp + p);  // 2 px

        float4 r0 = sample_one(plane, sv.x, sv.y);
        float4 r1 = sample_one(plane, sv.z, sv.w);

        *reinterpret_cast<float2*>(o0 + p) = make_float2(r0.x, r1.x);
        *reinterpret_cast<float2*>(o1 + p) = make_float2(r0.y, r1.y);
        *reinterpret_cast<float2*>(o2 + p) = make_float2(r0.z, r1.z);
        *reinterpret_cast<float2*>(o3 + p) = make_float2(r0.w, r1.w);
    }
}

extern "C" void kernel_launch(void* const* d_in, const int* in_sizes, int n_in,
                              void* d_out, int out_size)
{
    const float* x      = (const float*)d_in[0];
    const float* weight = (const float*)d_in[1];
    const float* bias   = (const float*)d_in[2];
    float* out          = (float*)d_out;

    dysample_stage1<<<1024, 256>>>(x, weight, bias);   // 16*64 (b,h) rows
    dysample_stage2<<<4096, 256>>>(out);               // (b, cg, quarter)
}